// round 17
// baseline (speedup 1.0000x reference)
#include <cuda_runtime.h>
#include <math.h>

#define NB_ 16
#define NC 64
#define NH 130
#define NKX 66
#define NM 12
#define NE 15
#define NR 4
#define HW (NH*NH)          /* 16900 */
#define BC (NB_*NC)         /* 1024 */

/* ---------------- scratch (device globals, no runtime allocation) -------- */
__device__ float  g_hA[BC*HW];
__device__ float  g_hB[BC*HW];
__device__ float2 g_Modes[BC*24*NM];
__device__ float2 g_OutModes[BC*24*NM];
__device__ float2 g_Ty[BC*NH*NM];
__device__ float  g_sab[BC];
__device__ float2 g_d1[NB_*NC*NC];
__device__ float2 g_d2[NB_*NC*NC];
__device__ float2 g_tw[NH];

__device__ __forceinline__ float gelu_exact(float v){
    return 0.5f*v*(1.f+erff(v*0.70710678118654752f));
}

/* twiddle table: tw[k] = (cos, sin)(2*pi*k/130) */
__global__ void ktw(){
    int k = threadIdx.x;
    if(k < NH){
        double th = 6.283185307179586476925286766559 * (double)k / 130.0;
        g_tw[k] = make_float2((float)cos(th), (float)sin(th));
    }
}

/* lift: h0[b,c,y,x] = concat(x,grid)@fc0_w + fc0_b ; zero pad region */
__global__ void k0(const float* __restrict__ xin, const float* __restrict__ grd,
                   const float* __restrict__ w, const float* __restrict__ bias){
    int y = blockIdx.x, b = blockIdx.y, tid = threadIdx.x;
    __shared__ float in[128*12];
    __shared__ float ws[12*NC];
    __shared__ float bs[NC];
    for(int i=tid;i<12*NC;i+=256) ws[i]=w[i];
    if(tid<NC) bs[tid]=bias[tid];
    if(y<128){
        for(int i=tid;i<128*10;i+=256){ int xx=i/10,t=i%10; in[xx*12+t]=xin[(((size_t)b*128+y)*128+xx)*10+t]; }
        for(int i=tid;i<128*2 ;i+=256){ int xx=i/2 ,t=i%2 ; in[xx*12+10+t]=grd[(((size_t)b*128+y)*128+xx)*2+t]; }
    }
    __syncthreads();
    for(int idx=tid; idx<NC*NH; idx+=256){
        int c=idx/NH, xx=idx%NH;
        float v=0.f;
        if(y<128 && xx<128){
            v=bs[c];
            #pragma unroll
            for(int t=0;t<12;t++) v += in[xx*12+t]*ws[t*NC+c];
        }
        g_hA[(((size_t)b*NC+c)*NH+y)*NH+xx]=v;
    }
}

/* ===================== fused mixed-radix 2D forward FFT ====================
 * 130 = 13*10.  Low-smem version + register twiddle recurrence in B/D. */
__global__ void __launch_bounds__(1024,2) kfft(int curA){
    extern __shared__ unsigned char s_raw[];
    float*  hs  = (float*)s_raw;            /* 130*132 floats; reused as Z/GC */
    float2* GA  = (float2*)(hs + 17160);    /* 65*78 = 5070 float2           */
    float2* tws = GA + 5070;                /* 130 */
    float2* w10 = tws + 130;                /* 100 */
    __shared__ float swred[32];
    int bc = blockIdx.x, tid = threadIdx.x;
    const float* hin = curA ? g_hA : g_hB;
    const float* hp = hin + (size_t)bc*HW;
    for(int i=tid;i<HW;i+=1024){ int y=i/130, x=i-y*130; hs[y*132+x]=hp[i]; }
    for(int i=tid;i<130;i+=1024) tws[i]=g_tw[i];
    for(int i=tid;i<100;i+=1024){ int r=i/10,p=i-r*10; w10[i]=g_tw[13*((r*p)%10)]; }
    __syncthreads();

    float2* zb = (float2*)hs;   /* Z[y][kx] : row y overlays h row y exactly */

    /* stages A+B in two y-halves (GA holds 65 rows) */
    for(int half=0; half<2; half++){
        int ybase = half*65;
        for(int it=tid; it<845; it+=1024){
            int yl = it/13, q = it-yl*13;
            int y = ybase + yl;
            float hv[10];
            #pragma unroll
            for(int p=0;p<10;p++) hv[p]=hs[y*132 + 13*p + q];
            float2* ga = GA + yl*78 + q*6;
            #pragma unroll
            for(int r=0;r<6;r++){
                float ar=0.f, ai=0.f;
                #pragma unroll
                for(int p=0;p<10;p++){
                    float2 w = w10[r*10+p];
                    ar += hv[p]*w.x;
                    ai -= hv[p]*w.y;
                }
                ga[r]=make_float2(ar,ai);
            }
        }
        __syncthreads();
        for(int it=tid; it<4290; it+=1024){
            int yl = it/66, kx = it-yl*66;
            int y = ybase + yl;
            int r = kx - (kx/10)*10;
            float sgn = 1.f;
            if(r>5){ r = 10-r; sgn = -1.f; }
            const float2* ga = GA + yl*78 + r;
            float2 wk = tws[kx];
            float wr=1.f, wi=0.f;
            float ar=0.f, ai=0.f;
            #pragma unroll
            for(int q=0;q<13;q++){
                float2 g = ga[q*6];
                float gy = g.y*sgn;
                ar += g.x*wr + gy*wi;
                ai += gy*wr - g.x*wi;
                float nr = wr*wk.x - wi*wk.y;
                wi = wr*wk.y + wi*wk.x;
                wr = nr;
            }
            zb[y*66+kx]=make_float2(ar,ai);
        }
        __syncthreads();
    }

    /* stage C: radix-10 along y, IN-PLACE in zb. */
    for(int it=tid; it<858; it+=1024){
        int q2 = it/66, kx = it-q2*66;
        float2 zp[10];
        #pragma unroll
        for(int p=0;p<10;p++) zp[p]=zb[(13*p+q2)*66 + kx];
        #pragma unroll
        for(int r=0;r<10;r++){
            float ar=0.f, ai=0.f;
            #pragma unroll
            for(int p=0;p<10;p++){
                float2 w = w10[r*10+p];
                ar += zp[p].x*w.x + zp[p].y*w.y;
                ai += zp[p].y*w.x - zp[p].x*w.y;
            }
            zb[(13*r+q2)*66 + kx]=make_float2(ar,ai);
        }
    }
    __syncthreads();

    /* stage D: finish y transform; kx-pair float4; register twiddle recurrence */
    float lsum=0.f;
    for(int it=tid; it<4290; it+=1024){
        int ky = it/33, kxp = it-ky*33, kx0 = kxp*2;
        int r2 = ky - (ky/10)*10;
        float2 wk = tws[ky];
        float wr=1.f, wi=0.f;
        float a0r=0.f,a0i=0.f,a1r=0.f,a1i=0.f;
        #pragma unroll
        for(int q=0;q<13;q++){
            float4 g = *(const float4*)(zb + (13*r2+q)*66 + kx0);
            a0r += g.x*wr + g.y*wi; a0i += g.y*wr - g.x*wi;
            a1r += g.z*wr + g.w*wi; a1i += g.w*wr - g.z*wi;
            float nr = wr*wk.x - wi*wk.y;
            wi = wr*wk.y + wi*wk.x;
            wr = nr;
        }
        lsum += sqrtf(a0r*a0r+a0i*a0i) + sqrtf(a1r*a1r+a1i*a1i);
        if(kx0<NM && (ky<NM || ky>=NH-NM)){
            int jr = (ky<NM)? ky : ky-106;
            g_Modes[((size_t)bc*24+jr)*NM+kx0  ]=make_float2(a0r,a0i);
            g_Modes[((size_t)bc*24+jr)*NM+kx0+1]=make_float2(a1r,a1i);
        }
    }
    for(int o=16;o>0;o>>=1) lsum += __shfl_down_sync(0xffffffffu, lsum, o);
    if((tid&31)==0) swred[tid>>5]=lsum;
    __syncthreads();
    if(tid<32){
        float s = swred[tid];
        for(int o=16;o>0;o>>=1) s += __shfl_down_sync(0xffffffffu, s, o);
        if(tid==0) g_sab[bc]=s/8580.f;
    }
}

/* fused MoE: gate softmax + d[b] = 0.1 * sum_e g[b,e] (A[e] @ B[e])
 * i-split x4 for occupancy: grid (b, which, islice); block stages a 16-row
 * A slice + full B; gate recomputed per block (trivial). */
__global__ void __launch_bounds__(256) kmoe(
        const float* __restrict__ A1, const float* __restrict__ B1,
        const float* __restrict__ A2, const float* __restrict__ B2,
        const float* __restrict__ gw, const float* __restrict__ gb){
    extern __shared__ unsigned char s_raw[];
    float2* As = (float2*)s_raw;          /* [e][i16][r] : 15*16*4 = 960 */
    float2* Bs = As + 960;                /* [e][r][o]  : 15*4*64 = 3840 */
    float*  lg = (float*)(Bs + 3840);     /* 16 */
    float*  gs = lg + 16;                 /* 16 */
    int b = blockIdx.x, which = blockIdx.y, isl = blockIdx.z, tid = threadIdx.x;
    int i0 = isl*16;
    const float2* A  = (const float2*)(which? A2:A1);
    const float2* Bm = (const float2*)(which? B2:B1);
    float2* dd = which? g_d2 : g_d1;
    for(int i=tid;i<960;i+=256){
        int e=i/64, ir=i%64;            /* ir = local_i*4 + r */
        As[i]=A[(e*NC + i0)*NR + ir];
    }
    for(int i=tid;i<3840;i+=256) Bs[i]=Bm[i];
    if(tid<NE){
        float s=gb[tid];
        for(int c=0;c<NC;c++) s += g_sab[b*NC+c]*gw[c*NE+tid];
        lg[tid]=s;
    }
    __syncthreads();
    if(tid==0){
        float mx=-1e30f;
        for(int i=0;i<NE;i++) mx=fmaxf(mx,lg[i]);
        float den=0.f;
        for(int i=0;i<NE;i++){ lg[i]=expf(lg[i]-mx); den+=lg[i]; }
        for(int i=0;i<NE;i++) gs[i]=lg[i]/den;
    }
    __syncthreads();
    for(int idx=tid; idx<16*NC; idx+=256){
        int il=idx>>6, o=idx&63;
        float rr=0.f, ri=0.f;
        #pragma unroll 3
        for(int e=0;e<NE;e++){
            float ge = gs[e];
            float er=0.f, ei=0.f;
            #pragma unroll
            for(int r=0;r<NR;r++){
                float2 a=As[(e*16+il)*NR+r];
                float2 b2=Bs[(e*NR+r)*NC+o];
                er += a.x*b2.x - a.y*b2.y;
                ei += a.x*b2.y + a.y*b2.x;
            }
            rr += ge*er; ri += ge*ei;
        }
        dd[b*NC*NC + (i0+il)*NC + o]=make_float2(0.1f*rr,0.1f*ri);
    }
}

/* mode mixing: o[b,o,p,q] = sum_i ft[b,i,p,q] * (W[i,o,p,q] + d[b,i,o])
 * pq-split x3 for occupancy/latency hiding. */
__global__ void __launch_bounds__(192) kmix(const float* __restrict__ W1,const float* __restrict__ W2){
    extern __shared__ unsigned char s_raw[];
    float2* tops = (float2*)s_raw;       /* 64*48 */
    float2* ds   = tops + NC*48;         /* 64*8  */
    int ot=blockIdx.x;
    int half=blockIdx.y/3, ps=blockIdx.y%3;
    int b=blockIdx.z;
    int pq0 = ps*48;
    const float2* W    = (const float2*)(half? W2:W1);
    const float2* dmat = half? g_d2 : g_d1;
    int jbase = half*NM;
    for(int i=threadIdx.x;i<NC*48;i+=192){
        int c=i/48, pq=pq0 + i%48;
        tops[i]=g_Modes[(((size_t)b*NC+c)*24 + jbase + pq/NM)*NM + pq%NM];
    }
    for(int i=threadIdx.x;i<NC*8;i+=192){
        int c=i/8, oo=i%8;
        ds[i]=dmat[((size_t)b*NC+c)*NC + ot*8+oo];
    }
    __syncthreads();
    for(int idx=threadIdx.x; idx<8*48; idx+=192){
        int oo=idx/48, pql=idx%48; int o=ot*8+oo; int pq=pq0+pql;
        float rr=0.f, ri=0.f;
        #pragma unroll 8
        for(int i=0;i<NC;i++){
            float2 t=tops[i*48+pql];
            float2 d=ds[i*8+oo];
            float2 w=W[((size_t)i*NC+o)*144+pq];
            float wr=w.x+d.x, wi=w.y+d.y;
            rr += t.x*wr - t.y*wi;
            ri += t.x*wi + t.y*wr;
        }
        g_OutModes[(((size_t)b*NC+o)*24 + jbase + pq/NM)*NM + pq%NM]=make_float2(rr,ri);
    }
}

/* inverse fft along y (only 24 nonzero bins): Ty[y,q]
 * blockDim 520 -> exactly 3 outputs/thread (no straggler pass). */
__global__ void __launch_bounds__(520) kinv1(){
    __shared__ float2 om[24*NM];
    __shared__ float2 tws[NH];
    int bc=blockIdx.x, tid=threadIdx.x;
    for(int i=tid;i<24*NM;i+=520) om[i]=g_OutModes[(size_t)bc*24*NM+i];
    for(int i=tid;i<NH;i+=520) tws[i]=g_tw[i];
    __syncthreads();
    for(int idx=tid; idx<NH*NM; idx+=520){
        int y=idx/NM, q=idx%NM;
        float rr=0.f, ri=0.f;
        #pragma unroll
        for(int j=0;j<24;j++){
            int ky = (j<NM)? j : j+106;
            int t = (ky*y)%NH;
            float2 w=tws[t];
            float2 o=om[j*NM+q];
            rr += o.x*w.x - o.y*w.y;
            ri += o.x*w.y + o.y*w.x;
        }
        g_Ty[(size_t)bc*NH*NM+idx]=make_float2(rr*(1.f/130.f), ri*(1.f/130.f));
    }
}

/* fused: irfft along x + pointwise conv + bias + (gelu) -> new h
 * blockDim 544: exactly ONE 16-output unit per thread (no stragglers). */
__global__ void __launch_bounds__(544) kfinal(int curA, const float* __restrict__ cw,
                       const float* __restrict__ cb, int dogelu){
    extern __shared__ unsigned char s_raw[];
    float*  hs   = (float*)s_raw;           /* 64*132 floats, x padded */
    float*  cws  = hs + NC*132;             /* 4096 */
    float*  cbs  = cws + NC*NC;             /* 64 */
    float2* tys  = (float2*)(cbs + NC);     /* 64*12 */
    float2* twsl = tys + NC*NM;             /* 130 */
    const float* hin  = curA ? g_hA : g_hB;
    float*       hout = curA ? g_hB : g_hA;
    int y=blockIdx.x, b=blockIdx.y, tid=threadIdx.x;
    for(int i=tid;i<NC*NH;i+=544){ int c=i/NH,x=i-c*NH; hs[c*132+x]=hin[(((size_t)b*NC+c)*NH+y)*NH+x]; }
    for(int i=tid;i<NC*2;i+=544){ int c=i>>1; hs[c*132+130+(i&1)]=0.f; }
    for(int i=tid;i<NC*NC;i+=544) cws[i]=cw[i];
    if(tid<NC) cbs[tid]=cb[tid];
    for(int i=tid;i<NC*NM;i+=544){ int c=i/NM,q=i-c*NM; tys[i]=g_Ty[((size_t)(b*NC+c)*NH+y)*NM+q]; }
    for(int i=tid;i<NH;i+=544) twsl[i]=g_tw[i];
    __syncthreads();
    const float4* h4 = (const float4*)hs;
    if(tid < 528){
        int u = tid;
        int g = u % 33, oq = u / 33;
        int o0 = oq*4, x0 = g*4;
        /* pointwise conv: 4 o x 4 x, h4 loads reused across o */
        float acc[4][4];
        #pragma unroll
        for(int o=0;o<4;o++){
            float c0=cbs[o0+o];
            acc[o][0]=c0; acc[o][1]=c0; acc[o][2]=c0; acc[o][3]=c0;
        }
        #pragma unroll 4
        for(int i4=0;i4<16;i4++){
            float4 h0=h4[(i4*4+0)*33+g];
            float4 h1=h4[(i4*4+1)*33+g];
            float4 h2=h4[(i4*4+2)*33+g];
            float4 h3=h4[(i4*4+3)*33+g];
            #pragma unroll
            for(int o=0;o<4;o++){
                float4 c = *(const float4*)(cws + (o0+o)*NC + i4*4);
                acc[o][0] += c.x*h0.x + c.y*h1.x + c.z*h2.x + c.w*h3.x;
                acc[o][1] += c.x*h0.y + c.y*h1.y + c.z*h2.y + c.w*h3.y;
                acc[o][2] += c.x*h0.z + c.y*h1.z + c.z*h2.z + c.w*h3.z;
                acc[o][3] += c.x*h0.w + c.y*h1.w + c.z*h2.w + c.w*h3.w;
            }
        }
        /* spectral irfft along x: per-a rotation by tw[x] per q step */
        float2 bw[4];
        #pragma unroll
        for(int a=0;a<4;a++){ int xx=x0+a; bw[a]=twsl[(xx<NH)?xx:0]; }
        #pragma unroll
        for(int o=0;o<4;o++){
            const float2* ty = tys + (o0+o)*NM;
            float2 t0=ty[0];
            float sac[4], wr[4], wi[4];
            #pragma unroll
            for(int a=0;a<4;a++){ sac[a]=t0.x; wr[a]=1.f; wi[a]=0.f; }
            #pragma unroll
            for(int q=1;q<NM;q++){
                float2 t=ty[q];
                #pragma unroll
                for(int a=0;a<4;a++){
                    float nr = wr[a]*bw[a].x - wi[a]*bw[a].y;
                    wi[a] = wr[a]*bw[a].y + wi[a]*bw[a].x;
                    wr[a] = nr;
                    sac[a] += 2.f*(t.x*wr[a] - t.y*wi[a]);
                }
            }
            float* op = hout + (((size_t)b*NC+o0+o)*NH+y)*NH;
            #pragma unroll
            for(int a=0;a<4;a++){
                int x=x0+a; if(x>=NH) break;
                float v = sac[a]*(1.f/130.f) + acc[o][a];
                if(dogelu) v = gelu_exact(v);
                op[x]=v;
            }
        }
    }
}

/* head: crop + fc1 + gelu + fc2.  fc1 weights read directly from gmem. */
__global__ void __launch_bounds__(128) kout(const float* __restrict__ f1w,
        const float* __restrict__ f1b, const float* __restrict__ f2w,
        const float* __restrict__ f2b, float* __restrict__ out){
    extern __shared__ unsigned char s_raw[];
    float* hs  = (float*)s_raw;     /* 64*128 */
    float* b1s = hs + 8192;         /* 128 */
    float* w2s = b1s + 128;         /* 128 */
    int y=blockIdx.x, b=blockIdx.y, tid=threadIdx.x;
    for(int i=tid;i<8192;i+=128){ int c=i>>7,x=i&127; hs[i]=g_hA[(((size_t)b*NC+c)*NH+y)*NH+x]; }
    if(tid<128){ b1s[tid]=f1b[tid]; w2s[tid]=f2w[tid]; }
    __syncthreads();
    int x=tid;
    float v[NC];
    #pragma unroll
    for(int i=0;i<NC;i++) v[i]=hs[i*128+x];
    const float4* w14 = (const float4*)f1w;
    float acc=f2b[0];
    for(int j=0;j<128;j+=4){
        float s0=b1s[j], s1=b1s[j+1], s2=b1s[j+2], s3=b1s[j+3];
        #pragma unroll
        for(int i=0;i<NC;i++){
            float4 w = __ldg(&w14[(i*128+j)>>2]);
            float vi = v[i];
            s0+=vi*w.x; s1+=vi*w.y; s2+=vi*w.z; s3+=vi*w.w;
        }
        acc += gelu_exact(s0)*w2s[j]   + gelu_exact(s1)*w2s[j+1]
             + gelu_exact(s2)*w2s[j+2] + gelu_exact(s3)*w2s[j+3];
    }
    out[((size_t)(b*128+y))*128+x]=acc;
}

/* ------------------------------- host ------------------------------------ */
extern "C" void kernel_launch(void* const* d_in, const int* in_sizes, int n_in,
                              void* d_out, int out_size){
    const float* x    =(const float*)d_in[0];
    const float* grd  =(const float*)d_in[1];
    const float* fc0w =(const float*)d_in[2];
    const float* fc0b =(const float*)d_in[3];
    const float* W1   =(const float*)d_in[4];
    const float* W2   =(const float*)d_in[5];
    const float* A1   =(const float*)d_in[6];
    const float* B1   =(const float*)d_in[7];
    const float* A2   =(const float*)d_in[8];
    const float* B2   =(const float*)d_in[9];
    const float* gw   =(const float*)d_in[10];
    const float* gb   =(const float*)d_in[11];
    const float* cw   =(const float*)d_in[12];
    const float* cb   =(const float*)d_in[13];
    const float* f1w  =(const float*)d_in[14];
    const float* f1b  =(const float*)d_in[15];
    const float* f2w  =(const float*)d_in[16];
    const float* f2b  =(const float*)d_in[17];
    float* out=(float*)d_out;

    const int SMFFT = 17160*4 + 5070*8 + 130*8 + 100*8;             /* 111040 */
    const int SMMOE = (960+3840)*8 + 32*4;                          /* 38528  */
    const int SMMIX = NC*48*8 + NC*8*8;                             /* 28672  */
    const int SMF   = (NC*132 + NC*NC + NC)*4 + (NC*NM + NH)*8;     /* 57616  */
    const int SMO   = (8192+128+128)*4;                             /* 33792  */

    cudaFuncSetAttribute(kfft,   cudaFuncAttributeMaxDynamicSharedMemorySize, SMFFT);
    cudaFuncSetAttribute(kmoe,   cudaFuncAttributeMaxDynamicSharedMemorySize, SMMOE);
    cudaFuncSetAttribute(kmix,   cudaFuncAttributeMaxDynamicSharedMemorySize, SMMIX);
    cudaFuncSetAttribute(kfinal, cudaFuncAttributeMaxDynamicSharedMemorySize, SMF);
    cudaFuncSetAttribute(kout,   cudaFuncAttributeMaxDynamicSharedMemorySize, SMO);

    ktw<<<1,160>>>();
    k0<<<dim3(NH,NB_),256>>>(x,grd,fc0w,fc0b);

    for(int l=0;l<4;l++){
        int curA = (l%2==0) ? 1 : 0;
        kfft<<<BC,1024,SMFFT>>>(curA);
        kmoe<<<dim3(NB_,2,4),256,SMMOE>>>(
            A1+(size_t)l*NE*NC*NR*2, B1+(size_t)l*NE*NR*NC*2,
            A2+(size_t)l*NE*NC*NR*2, B2+(size_t)l*NE*NR*NC*2,
            gw + (size_t)l*NC*NE, gb + (size_t)l*NE);
        kmix<<<dim3(8,6,NB_),192,SMMIX>>>(W1+(size_t)l*NC*NC*NM*NM*2,
                                          W2+(size_t)l*NC*NC*NM*NM*2);
        kinv1<<<BC,520>>>();
        kfinal<<<dim3(NH,NB_),544,SMF>>>(curA, cw+(size_t)l*NC*NC,
                                         cb+(size_t)l*NC, (l<3)?1:0);
    }
    kout<<<dim3(128,NB_),128,SMO>>>(f1w,f1b,f2w,f2b,out);
}